// round 12
// baseline (speedup 1.0000x reference)
#include <cuda_runtime.h>
#include <mma.h>
#include <cstdint>

using namespace nvcuda;

#define NP 256
#define NG 1024
#define F  128
#define EPSV 1e-5f

#define BP 16      // probes per block  (M = 32 rows = 16p x 2c interleaved)
#define BN 64      // gallery per block (N = 64)
#define KC 64      // K-chunk
#define THREADS 256
#define LDA 72
#define LDB 72
#define LDC 64

typedef wmma::fragment<wmma::matrix_a, 16, 16, 8, wmma::precision::tf32, wmma::row_major> FragA;
typedef wmma::fragment<wmma::matrix_b, 16, 16, 8, wmma::precision::tf32, wmma::col_major> FragB;
typedef wmma::fragment<wmma::accumulator, 16, 16, 8, float> FragC;

template <typename Frag>
__device__ __forceinline__ void split_tf32(Frag& hi, Frag& lo) {
    for (int e = 0; e < hi.num_elements; e++) {
        const float v = hi.x[e];
        const float hv = wmma::__float_to_tf32(v);
        hi.x[e] = hv;
        lo.x[e] = wmma::__float_to_tf32(v - hv);
    }
}

// out[p,g,c] = A2[p,c] + B2[g,c] + K[c] - 2 * sum_f (p_f w'_cf) g_f
// Cross term on tensor cores (tf32 wmma, 3xTF32 compensation). 256 blocks x 8 warps,
// 1 wmma tile per warp -> ~2 blocks/SM co-resident to hide block-serial latency.
__global__ void __launch_bounds__(THREADS) cls_kernel(
    const float* __restrict__ probe, const float* __restrict__ gal,
    const float* __restrict__ bnw, const float* __restrict__ bnb,
    const float* __restrict__ bnm, const float* __restrict__ bnv,
    const float* __restrict__ W, const float* __restrict__ bias,
    float* __restrict__ out)
{
    __shared__ __align__(16) float As[2 * BP * LDA];  // [m=2p+c][f_loc]; reused for cross spill
    __shared__ __align__(16) float Gs[BN * LDB];      // [g][f_loc]
    __shared__ __align__(16) float sW0[F];
    __shared__ __align__(16) float sW1[F];
    __shared__ float2 sA2[BP];
    __shared__ float2 sB2[BN];
    __shared__ float2 sK4[4];

    const int tid  = threadIdx.x;
    const int lane = tid & 31;
    const int warp = tid >> 5;       // 0..7
    const int bp = blockIdx.y * BP;
    const int bg = blockIdx.x * BN;

    // -------- folded weights + K reduction (threads 0..127, thread == feature) --------
    if (tid < F) {
        const int f = tid;
        const float inv = bnw[f] * rsqrtf(bnv[f] + EPSV);
        const float Wf0 = W[f], Wf1 = W[F + f];
        sW0[f] = Wf0 * inv;
        sW1[f] = Wf1 * inv;
        const float off = bnb[f] - bnm[f] * inv;
        float k0 = Wf0 * off, k1 = Wf1 * off;
        for (int o = 16; o > 0; o >>= 1) {
            k0 += __shfl_down_sync(0xffffffffu, k0, o);
            k1 += __shfl_down_sync(0xffffffffu, k1, o);
        }
        if (lane == 0)
            sK4[warp] = make_float2(k0 + (warp == 0 ? bias[0] : 0.f),
                                    k1 + (warp == 0 ? bias[1] : 0.f));
    }
    __syncthreads();

    // load mappings
    const int r = tid >> 4, q = tid & 15;    // probe: row r (0..15), col quad q
    const int g = tid >> 2, h = tid & 3;     // gallery: row g (0..63), col group h

    float pa0 = 0.f, pa1 = 0.f;              // A2 partial for probe r
    float gb0 = 0.f, gb1 = 0.f;              // B2 partial for gallery g

    const int mw = warp & 1;                 // m-tile (rows 16*mw..)
    const int nw = warp >> 1;                // n-tile (cols 16*nw..)
    FragC acc;
    wmma::fill_fragment(acc, 0.f);

    for (int kc = 0; kc < F; kc += KC) {
        __syncthreads();   // protect As/Gs from prior chunk's MMA reads

        // ---- A-tile: scaled probes, class-interleaved rows; fused A2 ----
        {
            const int col = 4 * q;
            const float4 x  = *(const float4*)(probe + (size_t)(bp + r) * F + kc + col);
            const float4 w0 = *(const float4*)&sW0[kc + col];
            const float4 w1 = *(const float4*)&sW1[kc + col];
            float4 a0, a1;
            a0.x = x.x * w0.x; a0.y = x.y * w0.y; a0.z = x.z * w0.z; a0.w = x.w * w0.w;
            a1.x = x.x * w1.x; a1.y = x.y * w1.y; a1.z = x.z * w1.z; a1.w = x.w * w1.w;
            *(float4*)&As[(2 * r)     * LDA + col] = a0;
            *(float4*)&As[(2 * r + 1) * LDA + col] = a1;
            pa0 += a0.x * x.x + a0.y * x.y + a0.z * x.z + a0.w * x.w;
            pa1 += a1.x * x.x + a1.y * x.y + a1.z * x.z + a1.w * x.w;
        }
        // ---- G-tile: raw gallery; fused B2 ----
        for (int j = 0; j < 4; j++) {
            const int col = 16 * h + 4 * j;
            const float4 x  = *(const float4*)(gal + (size_t)(bg + g) * F + kc + col);
            const float4 w0 = *(const float4*)&sW0[kc + col];
            const float4 w1 = *(const float4*)&sW1[kc + col];
            *(float4*)&Gs[g * LDB + col] = x;
            const float xx = x.x * x.x, yy = x.y * x.y, zz = x.z * x.z, ww = x.w * x.w;
            gb0 += w0.x * xx + w0.y * yy + w0.z * zz + w0.w * ww;
            gb1 += w1.x * xx + w1.y * yy + w1.z * zz + w1.w * ww;
        }
        __syncthreads();

        // ---- tensor mainloop: one 16x16 tile per warp, 3xTF32 ----
        for (int s = 0; s < 8; s++) {
            FragA a_hi, a_lo;
            FragB b_hi, b_lo;
            wmma::load_matrix_sync(a_hi, &As[(16 * mw) * LDA + 8 * s], LDA);
            wmma::load_matrix_sync(b_hi, &Gs[(16 * nw) * LDB + 8 * s], LDB);
            split_tf32(a_hi, a_lo);
            split_tf32(b_hi, b_lo);
            wmma::mma_sync(acc, a_hi, b_hi, acc);
            wmma::mma_sync(acc, a_hi, b_lo, acc);
            wmma::mma_sync(acc, a_lo, b_hi, acc);
        }
    }

    // -------- reduce diag partials --------
    pa0 += __shfl_down_sync(0xffffffffu, pa0, 8, 16);
    pa0 += __shfl_down_sync(0xffffffffu, pa0, 4, 16);
    pa0 += __shfl_down_sync(0xffffffffu, pa0, 2, 16);
    pa0 += __shfl_down_sync(0xffffffffu, pa0, 1, 16);
    pa1 += __shfl_down_sync(0xffffffffu, pa1, 8, 16);
    pa1 += __shfl_down_sync(0xffffffffu, pa1, 4, 16);
    pa1 += __shfl_down_sync(0xffffffffu, pa1, 2, 16);
    pa1 += __shfl_down_sync(0xffffffffu, pa1, 1, 16);
    if (q == 0) sA2[r] = make_float2(pa0, pa1);
    gb0 += __shfl_down_sync(0xffffffffu, gb0, 2, 4);
    gb0 += __shfl_down_sync(0xffffffffu, gb0, 1, 4);
    gb1 += __shfl_down_sync(0xffffffffu, gb1, 2, 4);
    gb1 += __shfl_down_sync(0xffffffffu, gb1, 1, 4);
    if (h == 0) sB2[g] = make_float2(gb0, gb1);

    __syncthreads();   // all MMA reads of As/Gs done before scratch reuse

    // -------- spill cross tiles into As region (stride LDC) --------
    wmma::store_matrix_sync(&As[(16 * mw) * LDC + 16 * nw], acc, LDC, wmma::mem_row_major);
    __syncthreads();

    // -------- epilogue: one probe-row quarter per thread --------
    const float2 K01 = make_float2(sK4[0].x + sK4[1].x + sK4[2].x + sK4[3].x,
                                   sK4[0].y + sK4[1].y + sK4[2].y + sK4[3].y);
    {
        const int i  = r;            // probe 0..15
        const int gg = 4 * q;        // gallery quad 0..60
        const float4 c0 = *(const float4*)&As[(2 * i)     * LDC + gg];
        const float4 c1 = *(const float4*)&As[(2 * i + 1) * LDC + gg];
        const float2 a2 = sA2[i];
        const float ax = a2.x + K01.x;
        const float ay = a2.y + K01.y;
        const float2 b0 = sB2[gg], b1 = sB2[gg + 1], b2 = sB2[gg + 2], b3 = sB2[gg + 3];
        float4 o0, o1;
        o0.x = fmaf(-2.0f, c0.x, ax + b0.x);
        o0.y = fmaf(-2.0f, c1.x, ay + b0.y);
        o0.z = fmaf(-2.0f, c0.y, ax + b1.x);
        o0.w = fmaf(-2.0f, c1.y, ay + b1.y);
        o1.x = fmaf(-2.0f, c0.z, ax + b2.x);
        o1.y = fmaf(-2.0f, c1.z, ay + b2.y);
        o1.z = fmaf(-2.0f, c0.w, ax + b3.x);
        o1.w = fmaf(-2.0f, c1.w, ay + b3.y);
        float4* dst = (float4*)(out + ((size_t)(bp + i) * NG + bg + gg) * 2);
        dst[0] = o0;
        dst[1] = o1;
    }
}

// ---------------- launch: ONE kernel ----------------
extern "C" void kernel_launch(void* const* d_in, const int* in_sizes, int n_in,
                              void* d_out, int out_size) {
    const float* probe = (const float*)d_in[0];
    const float* gal   = (const float*)d_in[1];
    const float* bnw   = (const float*)d_in[2];
    const float* bnb   = (const float*)d_in[3];
    const float* bnm   = (const float*)d_in[4];
    const float* bnv   = (const float*)d_in[5];
    const float* W     = (const float*)d_in[6];
    const float* bias  = (const float*)d_in[7];
    float* out = (float*)d_out;

    dim3 grid(NG / BN, NP / BP);   // (16, 16) = 256 blocks x 256 threads
    cls_kernel<<<grid, THREADS>>>(probe, gal, bnw, bnb, bnm, bnv, W, bias, out);
}